// round 4
// baseline (speedup 1.0000x reference)
#include <cuda_runtime.h>
#include <cuda_fp16.h>
#include <cuda_bf16.h>

#define RES   256
#define RANK  12
#define OUTC  8

// Pass-1 output: projected planes fp16, 16B/texel. 3 MB.
__device__ uint4 g_planes_h[3][RES * RES];
// Pass-2 output: corner-quad records, 64B/texel (4 x uint4), border clamp baked.
// Layout: g_planes_q[((p<<16) | (y<<8) | x) * 4 + corner]. 12 MB.
__device__ uint4 g_planes_q[3 * RES * RES * 4];

// ---------------------------------------------------------------------------
// Pass 1: project 12 -> 8 channels via proj_w slice, store fp16.
// ---------------------------------------------------------------------------
__global__ void project_planes_kernel(const float* __restrict__ pxy,
                                      const float* __restrict__ pxz,
                                      const float* __restrict__ pyz,
                                      const float* __restrict__ W)
{
    const int p = blockIdx.y;
    const float* __restrict__ src = (p == 0) ? pxy : ((p == 1) ? pxz : pyz);

    __shared__ float w[OUTC][RANK];
    int t = threadIdx.x;
    if (t < OUTC * RANK) {
        int o = t / RANK;
        int k = t % RANK;
        w[o][k] = W[o * (3 * RANK) + p * RANK + k];
    }
    __syncthreads();

    int texel = blockIdx.x * blockDim.x + threadIdx.x;   // 0 .. 65535
    const float* __restrict__ in = src + (size_t)texel * RANK;

    float f[RANK];
    float4 i0 = __ldg((const float4*)(in));
    float4 i1 = __ldg((const float4*)(in + 4));
    float4 i2 = __ldg((const float4*)(in + 8));
    f[0]=i0.x; f[1]=i0.y; f[2]=i0.z; f[3]=i0.w;
    f[4]=i1.x; f[5]=i1.y; f[6]=i1.z; f[7]=i1.w;
    f[8]=i2.x; f[9]=i2.y; f[10]=i2.z; f[11]=i2.w;

    float o[OUTC];
    #pragma unroll
    for (int c = 0; c < OUTC; c++) {
        float s = 0.f;
        #pragma unroll
        for (int k = 0; k < RANK; k++) s = fmaf(f[k], w[c][k], s);
        o[c] = s;
    }

    __half2 h0 = __floats2half2_rn(o[0], o[1]);
    __half2 h1 = __floats2half2_rn(o[2], o[3]);
    __half2 h2 = __floats2half2_rn(o[4], o[5]);
    __half2 h3 = __floats2half2_rn(o[6], o[7]);
    uint4 packed;
    packed.x = *(unsigned int*)&h0;
    packed.y = *(unsigned int*)&h1;
    packed.z = *(unsigned int*)&h2;
    packed.w = *(unsigned int*)&h3;
    g_planes_h[p][texel] = packed;
}

// ---------------------------------------------------------------------------
// Pass 2: build 64B corner-quad records {v00, v01, v10, v11} with border clamp.
// ---------------------------------------------------------------------------
__global__ void build_quads_kernel()
{
    int t = blockIdx.x * blockDim.x + threadIdx.x;   // 0 .. 3*65536-1
    int p   = t >> 16;
    int idx = t & 0xFFFF;
    int y   = idx >> 8;
    int x   = idx & 0xFF;
    int x1  = (x < RES - 1) ? x + 1 : x;
    int y1  = (y < RES - 1) ? y + 1 : y;

    const uint4* src = g_planes_h[p];
    uint4 v00 = src[y  * RES + x ];
    uint4 v01 = src[y  * RES + x1];
    uint4 v10 = src[y1 * RES + x ];
    uint4 v11 = src[y1 * RES + x1];

    uint4* dst = &g_planes_q[(size_t)t * 4];
    dst[0] = v00;
    dst[1] = v01;
    dst[2] = v10;
    dst[3] = v11;
}

// ---------------------------------------------------------------------------
// Main kernel: 4 lanes per point, one per bilinear corner. Each plane sample
// is ONE load instruction whose quad addresses are contiguous 64B (aligned)
// -> exactly 1 L1 wavefront per plane per point.
// ---------------------------------------------------------------------------
__device__ __forceinline__ void plane_accum(int p, float ca, float cb,
                                            float ox, float sx, float oy, float sy,
                                            int c,
                                            __half2& h0, __half2& h1,
                                            __half2& h2, __half2& h3)
{
    // unnormalize (align_corners=False) + border clamp (subsumes coord clip)
    float ix = fminf(fmaxf(fmaf(ca, 128.f, 127.5f), 0.f), 255.f);
    float iy = fminf(fmaxf(fmaf(cb, 128.f, 127.5f), 0.f), 255.f);
    float x0f = floorf(ix);
    float y0f = floorf(iy);
    float wx = ix - x0f;
    float wy = iy - y0f;

    // this lane's corner weight: (c&1 ? wx : 1-wx) * (c>>1 ? wy : 1-wy)
    float wxc = fmaf(sx, wx, ox);
    float wyc = fmaf(sy, wy, oy);
    __half2 ws2 = __float2half2_rn(wxc * wyc);

    int x0 = (int)x0f;
    int y0 = (int)y0f;
    int off = (((p << 16) | (y0 << 8) | x0) << 2) + c;
    uint4 u = __ldg(&g_planes_q[off]);

    h0 = __hfma2(*(__half2*)&u.x, ws2, h0);
    h1 = __hfma2(*(__half2*)&u.y, ws2, h1);
    h2 = __hfma2(*(__half2*)&u.z, ws2, h2);
    h3 = __hfma2(*(__half2*)&u.w, ws2, h3);
}

__global__ void __launch_bounds__(256)
geo_encoder_kernel(const float* __restrict__ coords,
                   const float* __restrict__ proj_b,
                   float* __restrict__ out,
                   int N)
{
    int t = blockIdx.x * blockDim.x + threadIdx.x;
    int i = t >> 2;          // point index
    if (i >= N) return;
    int c = t & 3;           // corner: bit0 = x side, bit1 = y side

    // one coalesced lane-load + quad broadcast instead of 3 loads x 4 lanes
    float v = (c < 3) ? __ldg(coords + 3 * (size_t)i + c) : 0.f;
    float cx = __shfl_sync(0xffffffffu, v, 0, 4);
    float cy = __shfl_sync(0xffffffffu, v, 1, 4);
    float cz = __shfl_sync(0xffffffffu, v, 2, 4);

    // corner weight affine params: w_side = o + s*w
    float fx = (float)(c & 1);
    float fy = (float)(c >> 1);
    float sx = 2.f * fx - 1.f;   // -1 or +1
    float ox = 1.f - fx;         //  1 or  0
    float sy = 2.f * fy - 1.f;
    float oy = 1.f - fy;

    __half2 z = __float2half2_rn(0.f);
    __half2 h0 = z, h1 = z, h2 = z, h3 = z;

    plane_accum(0, cx, cy, ox, sx, oy, sy, c, h0, h1, h2, h3);  // xy
    plane_accum(1, cx, cz, ox, sx, oy, sy, c, h0, h1, h2, h3);  // xz
    plane_accum(2, cy, cz, ox, sx, oy, sy, c, h0, h1, h2, h3);  // yz

    // upconvert lane partials, then fp32 quad butterfly reduction
    float2 f0 = __half22float2(h0);
    float2 f1 = __half22float2(h1);
    float2 f2 = __half22float2(h2);
    float2 f3 = __half22float2(h3);
    float a[8] = { f0.x, f0.y, f1.x, f1.y, f2.x, f2.y, f3.x, f3.y };

    #pragma unroll
    for (int k = 0; k < 8; k++) {
        a[k] += __shfl_xor_sync(0xffffffffu, a[k], 1);
        a[k] += __shfl_xor_sync(0xffffffffu, a[k], 2);
    }

    // lanes c=0,1 each write 16B of the 32B output record
    if (c < 2) {
        float4 bias = __ldg((const float4*)proj_b + c);
        int b = c * 4;
        float o0 = fminf(fmaxf(a[b + 0] + bias.x, -10.f), 10.f);
        float o1 = fminf(fmaxf(a[b + 1] + bias.y, -10.f), 10.f);
        float o2 = fminf(fmaxf(a[b + 2] + bias.z, -10.f), 10.f);
        float o3 = fminf(fmaxf(a[b + 3] + bias.w, -10.f), 10.f);
        ((float4*)(out + 8 * (size_t)i))[c] = make_float4(o0, o1, o2, o3);
    }
}

extern "C" void kernel_launch(void* const* d_in, const int* in_sizes, int n_in,
                              void* d_out, int out_size)
{
    const float* coords = (const float*)d_in[0];
    const float* pxy    = (const float*)d_in[1];
    const float* pxz    = (const float*)d_in[2];
    const float* pyz    = (const float*)d_in[3];
    const float* projw  = (const float*)d_in[4];
    const float* projb  = (const float*)d_in[5];
    float* out = (float*)d_out;

    int N = in_sizes[0] / 3;

    dim3 pgrid(RES * RES / 256, 3);
    project_planes_kernel<<<pgrid, 256>>>(pxy, pxz, pyz, projw);

    build_quads_kernel<<<3 * RES * RES / 256, 256>>>();

    long long threads = 4LL * N;
    int blocks = (int)((threads + 255) / 256);
    geo_encoder_kernel<<<blocks, 256>>>(coords, projb, out, N);
}

// round 5
// speedup vs baseline: 1.1813x; 1.1813x over previous
#include <cuda_runtime.h>
#include <cuda_fp16.h>
#include <cuda_bf16.h>

#define RES   256
#define RANK  12
#define OUTC  8

// Corner-quad records: per (plane,y,x) a 64B record {v00,v01,v10,v11} of
// fp16x8 projected features, border clamp baked in. 12 MB, L2-resident.
__device__ uint4 g_planes_q[3 * RES * RES * 4];

// ---------------------------------------------------------------------------
// Fused prolog: project 12->8ch (proj_w slice) for the 4 corners of each
// texel and store one 64B quad record. Replaces the old 2-pass prolog.
// ---------------------------------------------------------------------------
__device__ __forceinline__ uint4 project_texel(const float* __restrict__ src,
                                               int idx, const float (*w)[RANK])
{
    const float* in = src + (size_t)idx * RANK;
    float4 i0 = __ldg((const float4*)(in));
    float4 i1 = __ldg((const float4*)(in + 4));
    float4 i2 = __ldg((const float4*)(in + 8));
    float f[RANK] = { i0.x,i0.y,i0.z,i0.w, i1.x,i1.y,i1.z,i1.w, i2.x,i2.y,i2.z,i2.w };

    float o[OUTC];
    #pragma unroll
    for (int c = 0; c < OUTC; c++) {
        float s = 0.f;
        #pragma unroll
        for (int k = 0; k < RANK; k++) s = fmaf(f[k], w[c][k], s);
        o[c] = s;
    }
    __half2 h0 = __floats2half2_rn(o[0], o[1]);
    __half2 h1 = __floats2half2_rn(o[2], o[3]);
    __half2 h2 = __floats2half2_rn(o[4], o[5]);
    __half2 h3 = __floats2half2_rn(o[6], o[7]);
    uint4 r;
    r.x = *(unsigned int*)&h0; r.y = *(unsigned int*)&h1;
    r.z = *(unsigned int*)&h2; r.w = *(unsigned int*)&h3;
    return r;
}

__global__ void build_quads_kernel(const float* __restrict__ pxy,
                                   const float* __restrict__ pxz,
                                   const float* __restrict__ pyz,
                                   const float* __restrict__ W)
{
    const int p = blockIdx.y;
    const float* __restrict__ src = (p == 0) ? pxy : ((p == 1) ? pxz : pyz);

    __shared__ float w[OUTC][RANK];
    int t = threadIdx.x;
    if (t < OUTC * RANK) {
        int o = t / RANK, k = t % RANK;
        w[o][k] = W[o * (3 * RANK) + p * RANK + k];
    }
    __syncthreads();

    int texel = blockIdx.x * blockDim.x + threadIdx.x;   // 0 .. 65535
    int y = texel >> 8, x = texel & 0xFF;
    int x1 = (x < RES - 1) ? x + 1 : x;
    int y1 = (y < RES - 1) ? y + 1 : y;

    uint4* dst = &g_planes_q[((size_t)(p << 16 | texel)) << 2];
    dst[0] = project_texel(src, y  * RES + x , w);
    dst[1] = project_texel(src, y  * RES + x1, w);
    dst[2] = project_texel(src, y1 * RES + x , w);
    dst[3] = project_texel(src, y1 * RES + x1, w);
}

// ---------------------------------------------------------------------------
// Main kernel: 4 lanes per 2 points; lane c handles corner c of both points.
// Each plane sample = ONE LDG.128 into a 64B-aligned quad -> 1 wavefront.
// ---------------------------------------------------------------------------
__device__ __forceinline__ void point_accum(float cx, float cy, float cz,
                                            int c, float sx, float ox,
                                            float sy, float oy,
                                            __half2 acc[4])
{
    // per-coordinate transform, once (subsumes coord clip)
    float tx = fminf(fmaxf(fmaf(cx, 128.f, 127.5f), 0.f), 255.f);
    float ty = fminf(fmaxf(fmaf(cy, 128.f, 127.5f), 0.f), 255.f);
    float tz = fminf(fmaxf(fmaf(cz, 128.f, 127.5f), 0.f), 255.f);
    float fx = floorf(tx), fy = floorf(ty), fz = floorf(tz);
    float wx = tx - fx, wy = ty - fy, wz = tz - fz;
    int x0 = (int)fx, y0 = (int)fy, z0 = (int)fz;

    // lane-side weights: first-axis uses corner bit0 (sx,ox), second-axis bit1
    float u_x = fmaf(sx, wx, ox);   // x as first axis (planes xy, xz)
    float u_y = fmaf(sx, wy, ox);   // y as first axis (plane yz)
    float v_y = fmaf(sy, wy, oy);   // y as second axis (plane xy)
    float v_z = fmaf(sy, wz, oy);   // z as second axis (planes xz, yz)

    __half2 w0 = __float2half2_rn(u_x * v_y);
    __half2 w1 = __float2half2_rn(u_x * v_z);
    __half2 w2 = __float2half2_rn(u_y * v_z);

    int o0 = ((          (y0 << 8) | x0) << 2) + c;
    int o1 = (((1 << 16) | (z0 << 8) | x0) << 2) + c;
    int o2 = (((2 << 16) | (z0 << 8) | y0) << 2) + c;

    uint4 a = __ldg(&g_planes_q[o0]);
    uint4 b = __ldg(&g_planes_q[o1]);
    uint4 d = __ldg(&g_planes_q[o2]);

    acc[0] = __hfma2(*(__half2*)&a.x, w0, acc[0]);
    acc[1] = __hfma2(*(__half2*)&a.y, w0, acc[1]);
    acc[2] = __hfma2(*(__half2*)&a.z, w0, acc[2]);
    acc[3] = __hfma2(*(__half2*)&a.w, w0, acc[3]);
    acc[0] = __hfma2(*(__half2*)&b.x, w1, acc[0]);
    acc[1] = __hfma2(*(__half2*)&b.y, w1, acc[1]);
    acc[2] = __hfma2(*(__half2*)&b.z, w1, acc[2]);
    acc[3] = __hfma2(*(__half2*)&b.w, w1, acc[3]);
    acc[0] = __hfma2(*(__half2*)&d.x, w2, acc[0]);
    acc[1] = __hfma2(*(__half2*)&d.y, w2, acc[1]);
    acc[2] = __hfma2(*(__half2*)&d.z, w2, acc[2]);
    acc[3] = __hfma2(*(__half2*)&d.w, w2, acc[3]);
}

__device__ __forceinline__ __half2 hshfl_add(__half2 v, int lanemask) {
    unsigned int u = *(unsigned int*)&v;
    unsigned int s = __shfl_xor_sync(0xffffffffu, u, lanemask);
    return __hadd2(v, *(__half2*)&s);
}

__global__ void __launch_bounds__(256)
geo_encoder_kernel(const float* __restrict__ coords,
                   const float* __restrict__ proj_b,
                   float* __restrict__ out,
                   int N)
{
    int t = blockIdx.x * blockDim.x + threadIdx.x;
    int g = t >> 2;              // point-pair index (points 2g, 2g+1)
    int iA = 2 * g;
    if (iA >= N) return;
    int c = t & 3;               // corner: bit0 = x side, bit1 = y side
    bool hasB = (iA + 1) < N;

    // coords for both points: 6 floats via 2 lane-loads + 6 narrow shuffles
    size_t base = 6 * (size_t)g;
    float v0 = (c < 3 || hasB) ? __ldg(coords + base + c) : 0.f;
    float v1 = (c < 2 && hasB) ? __ldg(coords + base + 4 + c) : 0.f;
    float cxA = __shfl_sync(0xffffffffu, v0, 0, 4);
    float cyA = __shfl_sync(0xffffffffu, v0, 1, 4);
    float czA = __shfl_sync(0xffffffffu, v0, 2, 4);
    float cxB = __shfl_sync(0xffffffffu, v0, 3, 4);
    float cyB = __shfl_sync(0xffffffffu, v1, 0, 4);
    float czB = __shfl_sync(0xffffffffu, v1, 1, 4);

    float fxc = (float)(c & 1);
    float fyc = (float)(c >> 1);
    float sx = 2.f * fxc - 1.f, ox = 1.f - fxc;
    float sy = 2.f * fyc - 1.f, oy = 1.f - fyc;

    __half2 z = __float2half2_rn(0.f);
    __half2 accA[4] = { z, z, z, z };
    __half2 accB[4] = { z, z, z, z };

    point_accum(cxA, cyA, czA, c, sx, ox, sy, oy, accA);
    if (hasB) point_accum(cxB, cyB, czB, c, sx, ox, sy, oy, accB);

    // quad butterfly reduction in half2 (8 shfl+hadd2 per point)
    #pragma unroll
    for (int r = 0; r < 4; r++) {
        accA[r] = hshfl_add(accA[r], 1);
        accA[r] = hshfl_add(accA[r], 2);
        accB[r] = hshfl_add(accB[r], 1);
        accB[r] = hshfl_add(accB[r], 2);
    }

    // lane c writes float4 #c of the pair's 64B output record:
    // c=0: ptA ch0-3, c=1: ptA ch4-7, c=2: ptB ch0-3, c=3: ptB ch4-7
    __half2 s0 = (c & 2) ? accB[(c & 1) * 2]     : accA[(c & 1) * 2];
    __half2 s1 = (c & 2) ? accB[(c & 1) * 2 + 1] : accA[(c & 1) * 2 + 1];
    float2 f0 = __half22float2(s0);
    float2 f1 = __half22float2(s1);

    float4 bias = __ldg((const float4*)proj_b + (c & 1));
    float o0 = fminf(fmaxf(f0.x + bias.x, -10.f), 10.f);
    float o1 = fminf(fmaxf(f0.y + bias.y, -10.f), 10.f);
    float o2 = fminf(fmaxf(f1.x + bias.z, -10.f), 10.f);
    float o3 = fminf(fmaxf(f1.y + bias.w, -10.f), 10.f);

    if (c < 2 || hasB)
        ((float4*)(out + 16 * (size_t)g))[c] = make_float4(o0, o1, o2, o3);
}

extern "C" void kernel_launch(void* const* d_in, const int* in_sizes, int n_in,
                              void* d_out, int out_size)
{
    const float* coords = (const float*)d_in[0];
    const float* pxy    = (const float*)d_in[1];
    const float* pxz    = (const float*)d_in[2];
    const float* pyz    = (const float*)d_in[3];
    const float* projw  = (const float*)d_in[4];
    const float* projb  = (const float*)d_in[5];
    float* out = (float*)d_out;

    int N = in_sizes[0] / 3;

    dim3 qgrid(RES * RES / 256, 3);
    build_quads_kernel<<<qgrid, 256>>>(pxy, pxz, pyz, projw);

    long long pairs = (N + 1) / 2;
    long long threads = 4LL * pairs;
    int blocks = (int)((threads + 255) / 256);
    geo_encoder_kernel<<<blocks, 256>>>(coords, projb, out, N);
}